// round 7
// baseline (speedup 1.0000x reference)
#include <cuda_runtime.h>
#include <cuda_bf16.h>
#include <cuda_fp16.h>
#include <cstdint>
#include <math.h>

#define BATCH 4
#define P 2048
#define D 1024
#define M_TOTAL (BATCH * P)     // 8192
#define NUM_ROUTES 8
#define NEG_BIG -3.0e38f
#define MASK_VAL -60000.0f

#define X_SCALE 16.0f           // 2^4
#define W_SCALE 1024.0f         // 2^10
#define INV_SCALE (1.0f / 16384.0f)  // 2^-14

#define OUT_W_OFF  (M_TOTAL * NUM_ROUTES)
#define OUT_F_OFF  (2 * M_TOTAL * NUM_ROUTES)

// ---------------- scratch (__device__ globals; no allocation allowed) -------
__device__ __half g_xs0[(size_t)M_TOTAL * D];
__device__ __half g_xs1[(size_t)M_TOTAL * D];
__device__ __half g_ws[3][2][(size_t)D * D];   // [which][split], scaled by 2^10
__device__ float g_q[(size_t)M_TOTAL * D];     // raw (unnormalized) fp32
__device__ float g_k[(size_t)M_TOTAL * D];     // raw (unnormalized) fp32
__device__ float g_v[(size_t)M_TOTAL * D];
__device__ float g_qn[M_TOTAL];                // row norms
__device__ float g_kn[M_TOTAL];
__device__ __half g_qh[(size_t)M_TOTAL * D];   // raw q, fp16
__device__ __half g_kh[(size_t)M_TOTAL * D];   // normalized k, fp16
__device__ uint32_t g_cand[(size_t)M_TOTAL * 128];  // 8 blocks x 16 packed cands/row

// ---------------- PTX helpers (compute_103-safe) ----------------------------
__device__ __forceinline__ uint32_t cvta_smem(const void* p) {
    return (uint32_t)__cvta_generic_to_shared(p);
}
__device__ __forceinline__ void cp16(uint32_t saddr, const void* gaddr) {
    asm volatile("cp.async.cg.shared.global [%0], [%1], 16;\n"
                 :: "r"(saddr), "l"(gaddr));
}
__device__ __forceinline__ void cp_commit() { asm volatile("cp.async.commit_group;\n"); }
__device__ __forceinline__ void cp_wait1() {
    asm volatile("cp.async.wait_group 1;\n" ::: "memory");
}
__device__ __forceinline__ void cp_wait_all() {
    asm volatile("cp.async.wait_group 0;\n" ::: "memory");
}
__device__ __forceinline__ void ldm4(uint32_t& r0, uint32_t& r1, uint32_t& r2, uint32_t& r3,
                                     uint32_t addr) {
    asm volatile("ldmatrix.sync.aligned.m8n8.x4.shared.b16 {%0,%1,%2,%3}, [%4];"
                 : "=r"(r0), "=r"(r1), "=r"(r2), "=r"(r3) : "r"(addr));
}
__device__ __forceinline__ void mma16816(float* d, const uint32_t* a, const uint32_t* b) {
    asm volatile(
        "mma.sync.aligned.m16n8k16.row.col.f32.f16.f16.f32 "
        "{%0,%1,%2,%3}, {%4,%5,%6,%7}, {%8,%9}, {%0,%1,%2,%3};"
        : "+f"(d[0]), "+f"(d[1]), "+f"(d[2]), "+f"(d[3])
        : "r"(a[0]), "r"(a[1]), "r"(a[2]), "r"(a[3]), "r"(b[0]), "r"(b[1]));
}
// order-preserving u32 key for fp32 (monotone: f1 < f2 <=> key1 < key2)
__device__ __forceinline__ uint32_t order32(float f) {
    uint32_t u = __float_as_uint(f);
    return u ^ (uint32_t)(((int32_t)u >> 31) | 0x80000000);
}

// ---------------- split / convert helpers ------------------------------------
__device__ __forceinline__ void split2(float f, __half& a0, __half& a1) {
    a0 = __float2half_rn(f);
    a1 = __float2half_rn(f - __half2float(a0));
}
__device__ __forceinline__ uint2 pack4h(__half a, __half b, __half c, __half d) {
    uint2 r;
    r.x = (uint32_t)__half_as_ushort(a) | ((uint32_t)__half_as_ushort(b) << 16);
    r.y = (uint32_t)__half_as_ushort(c) | ((uint32_t)__half_as_ushort(d) << 16);
    return r;
}

__global__ __launch_bounds__(256) void split_x_kernel(const float* __restrict__ x) {
    size_t e = ((size_t)blockIdx.x * 256 + threadIdx.x) * 4;
    int row = (int)(e >> 10);
    int col = (int)(e & 1023);
    int xrow = row + (row >> 11) + 1;    // skip token 0 of each batch
    float4 f = *(const float4*)(x + (size_t)xrow * D + col);
    __half a0[4], a1[4];
    split2(f.x * X_SCALE, a0[0], a1[0]);
    split2(f.y * X_SCALE, a0[1], a1[1]);
    split2(f.z * X_SCALE, a0[2], a1[2]);
    split2(f.w * X_SCALE, a0[3], a1[3]);
    *(uint2*)(g_xs0 + e) = pack4h(a0[0], a0[1], a0[2], a0[3]);
    *(uint2*)(g_xs1 + e) = pack4h(a1[0], a1[1], a1[2], a1[3]);
}

__global__ __launch_bounds__(256) void split_w_kernel(
    const float* __restrict__ Wq, const float* __restrict__ Wk, const float* __restrict__ Wv) {
    const int z = blockIdx.y;
    const float* W = (z == 0) ? Wq : (z == 1) ? Wk : Wv;
    size_t e = ((size_t)blockIdx.x * 256 + threadIdx.x) * 4;
    float4 f = *(const float4*)(W + e);
    __half a0[4], a1[4];
    split2(f.x * W_SCALE, a0[0], a1[0]);
    split2(f.y * W_SCALE, a0[1], a1[1]);
    split2(f.z * W_SCALE, a0[2], a1[2]);
    split2(f.w * W_SCALE, a0[3], a1[3]);
    *(uint2*)(g_ws[z][0] + e) = pack4h(a0[0], a0[1], a0[2], a0[3]);
    *(uint2*)(g_ws[z][1] + e) = pack4h(a1[0], a1[1], a1[2], a1[3]);
}

// ---------------- GEMM machinery: BK=64, 3-stage cp.async pipeline -----------
#define STAGES 3
#define SM_PER_BUF 55296
#define A_BYTES 18432
#define GEMM_SMEM (STAGES * SM_PER_BUF)

__device__ __forceinline__ void load_chunk(uint32_t st,
    const __half* __restrict__ Ag, const __half* __restrict__ Bg,
    int m0, int n0, int kc, int tid)
{
    const uint32_t sA = st, sB = st + A_BYTES;
#pragma unroll
    for (int t = 0; t < 4; t++) {
        int li = tid + t * 256;
        int row = li >> 3, seg = li & 7;
        cp16(sA + row * 144 + seg * 16, Ag + (size_t)(m0 + row) * D + kc * 64 + seg * 8);
    }
#pragma unroll
    for (int t = 0; t < 8; t++) {
        int li = tid + t * 256;
        int row = li >> 3, seg = li & 7;
        cp16(sB + row * 144 + seg * 16, Bg + (size_t)(n0 + row) * D + kc * 64 + seg * 8);
    }
}

__device__ __forceinline__ void compute_chunk(uint32_t st,
                                              float acc[4][8][4], int wr, int wc, int lane)
{
    const uint32_t sA = st, sB = st + A_BYTES;
    const int lr = lane & 15;
    const int lh = (lane >> 4) * 16;
#pragma unroll
    for (int ks = 0; ks < 4; ks++) {
        uint32_t a[4][4];
#pragma unroll
        for (int mi = 0; mi < 4; mi++)
            ldm4(a[mi][0], a[mi][1], a[mi][2], a[mi][3],
                 sA + (uint32_t)(wr * 64 + mi * 16 + lr) * 144 + ks * 32 + lh);
        uint32_t b[8][2];
#pragma unroll
        for (int njp = 0; njp < 4; njp++) {
            uint32_t r0, r1, r2, r3;
            ldm4(r0, r1, r2, r3,
                 sB + (uint32_t)(wc * 64 + njp * 16 + lr) * 144 + ks * 32 + lh);
            b[njp * 2][0] = r0; b[njp * 2][1] = r2;
            b[njp * 2 + 1][0] = r1; b[njp * 2 + 1][1] = r3;
        }
#pragma unroll
        for (int mi = 0; mi < 4; mi++)
#pragma unroll
            for (int nj = 0; nj < 8; nj++)
                mma16816(acc[mi][nj], a[mi], b[nj]);
    }
}

// ---------------- QKV GEMM (fp16x2 split; q/k: 3 combos, v: 1) ---------------
// grid (4, 64, 3); 16 k64-chunks per combo pass
__global__ __launch_bounds__(256, 1) void qkv_mma_kernel(
    const float* __restrict__ bq, const float* __restrict__ bk, const float* __restrict__ bv)
{
    extern __shared__ char dynsm[];
    const uint32_t sbase = cvta_smem(dynsm);

    const int z = blockIdx.z;
    const int m0 = blockIdx.y * 128, n0 = blockIdx.x * 256;
    const int tid = threadIdx.x, wid = tid >> 5, lane = tid & 31;
    const int wr = wid >> 2, wc = wid & 3;

    const __half* As[2] = { g_xs0, g_xs1 };
    const __half* Bs[2] = { g_ws[z][0], g_ws[z][1] };
    float* Cmat = (z == 0) ? g_q : (z == 1) ? g_k : g_v;
    const float* bias = (z == 0) ? bq : (z == 1) ? bk : bv;

    const int ca[3] = {0, 0, 1};
    const int cb[3] = {0, 1, 0};
    const int ncombo = (z == 2) ? 1 : 3;
    const int nch = ncombo * 16;

    float acc[4][8][4];
#pragma unroll
    for (int mi = 0; mi < 4; mi++)
#pragma unroll
        for (int nj = 0; nj < 8; nj++)
#pragma unroll
            for (int t = 0; t < 4; t++) acc[mi][nj][t] = 0.0f;

#pragma unroll
    for (int s = 0; s < STAGES - 1; s++) {
        load_chunk(sbase + s * SM_PER_BUF, As[ca[s >> 4]], Bs[cb[s >> 4]],
                   m0, n0, s & 15, tid);
        cp_commit();
    }

    for (int ch = 0; ch < nch; ch++) {
        cp_wait1();
        __syncthreads();
        const int ld = ch + STAGES - 1;
        if (ld < nch)
            load_chunk(sbase + (ld % 3) * SM_PER_BUF, As[ca[ld >> 4]], Bs[cb[ld >> 4]],
                       m0, n0, ld & 15, tid);
        cp_commit();
        compute_chunk(sbase + (ch % 3) * SM_PER_BUF, acc, wr, wc, lane);
    }

#pragma unroll
    for (int nj = 0; nj < 8; nj++) {
        const int n = n0 + wc * 64 + nj * 8 + (lane & 3) * 2;
        const float2 b2 = *(const float2*)(bias + n);
#pragma unroll
        for (int mi = 0; mi < 4; mi++) {
            const int row0 = m0 + wr * 64 + mi * 16 + (lane >> 2);
            float2 v0 = { fmaf(acc[mi][nj][0], INV_SCALE, b2.x),
                          fmaf(acc[mi][nj][1], INV_SCALE, b2.y) };
            float2 v1 = { fmaf(acc[mi][nj][2], INV_SCALE, b2.x),
                          fmaf(acc[mi][nj][3], INV_SCALE, b2.y) };
            *(float2*)(Cmat + (size_t)row0 * D + n) = v0;
            *(float2*)(Cmat + (size_t)(row0 + 8) * D + n) = v1;
        }
    }
}

// ---------------- scores GEMM + fused per-block top-16 candidates ------------
// scores[p, c] = q_raw[p] . k_hat[c] (same row-ranking as cosine sim).
// Epilogue: stage tile to smem as packed keys, each thread scans one row,
// writes top-16 candidate list for its 256-column block. grid (8, 16, 4).
#define SP_PITCH 260

__global__ __launch_bounds__(256, 1) void scores_mma_kernel()
{
    extern __shared__ char dynsm[];
    const uint32_t sbase = cvta_smem(dynsm);

    const int b = blockIdx.z;
    const int m0 = blockIdx.y * 128, n0 = blockIdx.x * 256;
    const int tid = threadIdx.x, wid = tid >> 5, lane = tid & 31;
    const int wr = wid >> 2, wc = wid & 3;

    const __half* Ag = g_qh + (size_t)b * P * D;
    const __half* Bg = g_kh + (size_t)b * P * D;

    float acc[4][8][4];
#pragma unroll
    for (int mi = 0; mi < 4; mi++)
#pragma unroll
        for (int nj = 0; nj < 8; nj++)
#pragma unroll
            for (int t = 0; t < 4; t++) acc[mi][nj][t] = 0.0f;

#pragma unroll
    for (int s = 0; s < STAGES - 1; s++) {
        load_chunk(sbase + s * SM_PER_BUF, Ag, Bg, m0, n0, s, tid);
        cp_commit();
    }

    for (int ch = 0; ch < 16; ch++) {
        cp_wait1();
        __syncthreads();
        const int ld = ch + STAGES - 1;
        if (ld < 16)
            load_chunk(sbase + (ld % 3) * SM_PER_BUF, Ag, Bg, m0, n0, ld, tid);
        cp_commit();
        compute_chunk(sbase + (ch % 3) * SM_PER_BUF, acc, wr, wc, lane);
    }

    // drain async copies, then reuse pipeline smem as a packed-score tile
    cp_wait_all();
    __syncthreads();
    uint32_t* sp = (uint32_t*)dynsm;   // [128][SP_PITCH]

#pragma unroll
    for (int nj = 0; nj < 8; nj++) {
        const int nl = wc * 64 + nj * 8 + (lane & 3) * 2;
#pragma unroll
        for (int mi = 0; mi < 4; mi++) {
            const int rl = wr * 64 + mi * 16 + (lane >> 2);
#pragma unroll
            for (int t = 0; t < 4; t++) {
                const int row = rl + (t >> 1) * 8;
                const int col = nl + (t & 1);
                float f = acc[mi][nj][t];
                if (m0 + row == n0 + col) f = MASK_VAL;   // diagonal
                sp[row * SP_PITCH + col] =
                    (order32(f) & 0xFFFFF800u) | (2047u - (uint32_t)(n0 + col));
            }
        }
    }
    __syncthreads();

    // per-row top-16 scan (128 threads, one row each)
    if (tid < 128) {
        uint32_t best[16];
#pragma unroll
        for (int i = 0; i < 16; i++) best[i] = 0u;
        const uint32_t* rp = sp + tid * SP_PITCH;
        for (int j = 0; j < 256; j++) {
            const uint32_t p = rp[j];
            if (p > best[15]) {
                best[15] = p;
                for (int pos = 15; pos > 0; pos--) {
                    if (best[pos - 1] < best[pos]) {
                        uint32_t tmp = best[pos - 1];
                        best[pos - 1] = best[pos];
                        best[pos] = tmp;
                    } else break;
                }
            }
        }
        uint32_t* dst = g_cand + ((size_t)(b * P + m0 + tid) * 8 + blockIdx.x) * 16;
#pragma unroll
        for (int i = 0; i < 16; i++) dst[i] = best[i];
    }
}

// ---------------- norms + fp16 operand prep ----------------------------------
// y=0: q row -> g_qn, g_qh (raw fp16).  y=1: k row -> g_kn, g_kh (normalized fp16)
__global__ __launch_bounds__(256) void norm_kernel() {
    const int r = blockIdx.x;
    const int tid = threadIdx.x;
    const bool isq = (blockIdx.y == 0);
    const float* row = (isq ? g_q : g_k) + (size_t)r * D;
    __half* hrow = (isq ? g_qh : g_kh) + (size_t)r * D;

    float4 v = ((const float4*)row)[tid];
    float s = v.x * v.x + v.y * v.y + v.z * v.z + v.w * v.w;
#pragma unroll
    for (int o = 16; o > 0; o >>= 1) s += __shfl_xor_sync(0xffffffffu, s, o);

    __shared__ float ws[8];
    if ((tid & 31) == 0) ws[tid >> 5] = s;
    __syncthreads();
    float tot = 0.0f;
#pragma unroll
    for (int w = 0; w < 8; w++) tot += ws[w];
    const float nrm = fmaxf(sqrtf(tot), 1e-12f);

    if (tid == 0) { if (isq) g_qn[r] = nrm; else g_kn[r] = nrm; }

    if (isq) {
        *(uint2*)(hrow + tid * 4) = pack4h(__float2half_rn(v.x), __float2half_rn(v.y),
                                           __float2half_rn(v.z), __float2half_rn(v.w));
    } else {
        const float inv = 1.0f / nrm;
        *(uint2*)(hrow + tid * 4) = pack4h(__float2half_rn(v.x * inv), __float2half_rn(v.y * inv),
                                           __float2half_rn(v.z * inv), __float2half_rn(v.w * inv));
    }
}

// ---------------- merge candidates -> fp32 rescue -> top-8 -> features -------
__global__ __launch_bounds__(256) void topk_kernel(float* __restrict__ out) {
    __shared__ float s_q[D];
    __shared__ int   s_c16[16];
    __shared__ float s_resc[16];
    __shared__ int   s_routes[8];
    __shared__ float s_vals[8];
    __shared__ float s_wn[8];

    const int r = blockIdx.x;
    const int b = r >> 11;
    const int tid = threadIdx.x, wid = tid >> 5, lane = tid & 31;

    // load raw q row into smem (for rescue dots)
    ((float4*)s_q)[tid] = ((const float4*)(g_q + (size_t)r * D))[tid];

    // Stage B: warp 0 merges 128 packed candidates -> global top-16 indices
    if (wid == 0) {
        const uint32_t* cl = g_cand + (size_t)r * 128;
        uint32_t c[4];
#pragma unroll
        for (int j = 0; j < 4; j++) c[j] = cl[lane * 4 + j];
        for (int it = 0; it < 16; it++) {
            uint32_t m = c[0];
#pragma unroll
            for (int j = 1; j < 4; j++) m = (c[j] > m) ? c[j] : m;
#pragma unroll
            for (int o = 16; o; o >>= 1) {
                uint32_t om = __shfl_xor_sync(0xffffffffu, m, o);
                m = (om > m) ? om : m;
            }
            if (lane == 0) s_c16[it] = 2047 - (int)(m & 0x7FFu);
#pragma unroll
            for (int j = 0; j < 4; j++) if (c[j] == m) c[j] = 0u;
        }
    }
    __syncthreads();

    // Stage C: fp32 rescue — exact cosine scores for 16 candidates (2 per warp)
    const float invqn = 1.0f / g_qn[r];
#pragma unroll
    for (int h = 0; h < 2; h++) {
        const int c = wid + h * 8;
        const int cand = s_c16[c];
        const float* krow = g_k + ((size_t)(b * P + cand)) * D;
        float acc = 0.0f;
#pragma unroll
        for (int i = 0; i < 8; i++) {
            const int off = i * 128 + lane * 4;
            float4 qa = *(const float4*)(s_q + off);
            float4 ka = *(const float4*)(krow + off);
            acc += qa.x * ka.x + qa.y * ka.y + qa.z * ka.z + qa.w * ka.w;
        }
#pragma unroll
        for (int o = 16; o; o >>= 1) acc += __shfl_xor_sync(0xffffffffu, acc, o);
        if (lane == 0) s_resc[c] = acc * invqn / g_kn[b * P + cand];
    }
    __syncthreads();

    // Stage D: warp 0 re-ranks 16 rescued candidates -> exact top-8
    if (wid == 0) {
        float val = (lane < 16) ? s_resc[lane] : NEG_BIG;
        int idx = (lane < 16) ? s_c16[lane] : 0x7fffffff;
        for (int rank = 0; rank < NUM_ROUTES; rank++) {
            float bvv = val; int bi = idx;
#pragma unroll
            for (int o = 16; o; o >>= 1) {
                float ov = __shfl_xor_sync(0xffffffffu, bvv, o);
                int oi = __shfl_xor_sync(0xffffffffu, bi, o);
                if (ov > bvv || (ov == bvv && oi < bi)) { bvv = ov; bi = oi; }
            }
            if (lane == 0) { s_routes[rank] = bi; s_vals[rank] = bvv; }
            if (idx == bi) val = NEG_BIG;
        }
    }
    __syncthreads();

    if (tid < NUM_ROUTES) {
        const float mx = s_vals[0];
        float sum = 0.0f;
#pragma unroll
        for (int j = 0; j < NUM_ROUTES; j++) sum += __expf((s_vals[j] - mx) * 10.0f);
        const float wn = __expf((s_vals[tid] - mx) * 10.0f) / sum;
        out[(size_t)r * NUM_ROUTES + tid] = (float)s_routes[tid];
        out[OUT_W_OFF + (size_t)r * NUM_ROUTES + tid] = wn;
        s_wn[tid] = wn;
    }
    __syncthreads();

    // Stage E: features
    const float* vb = g_v + (size_t)b * P * D;
    int rt[8]; float ww[8];
#pragma unroll
    for (int i = 0; i < 8; i++) { rt[i] = s_routes[i]; ww[i] = s_wn[i]; }
    const int d0 = tid * 4;
    float4 acc4 = {0.0f, 0.0f, 0.0f, 0.0f};
#pragma unroll
    for (int i = 0; i < 8; i++) {
        float4 vv = *(const float4*)(vb + (size_t)rt[i] * D + d0);
        acc4.x = fmaf(ww[i], vv.x, acc4.x);
        acc4.y = fmaf(ww[i], vv.y, acc4.y);
        acc4.z = fmaf(ww[i], vv.z, acc4.z);
        acc4.w = fmaf(ww[i], vv.w, acc4.w);
    }
    *(float4*)(out + OUT_F_OFF + (size_t)r * D + d0) = acc4;
}

// ---------------------------------------------------------------------------
extern "C" void kernel_launch(void* const* d_in, const int* in_sizes, int n_in,
                              void* d_out, int out_size) {
    const float* x  = (const float*)d_in[0];
    const float* Wq = (const float*)d_in[1];
    const float* bq = (const float*)d_in[2];
    const float* Wk = (const float*)d_in[3];
    const float* bk = (const float*)d_in[4];
    const float* Wv = (const float*)d_in[5];
    const float* bv = (const float*)d_in[6];
    float* out = (float*)d_out;

    cudaFuncSetAttribute(qkv_mma_kernel, cudaFuncAttributeMaxDynamicSharedMemorySize, GEMM_SMEM);
    cudaFuncSetAttribute(scores_mma_kernel, cudaFuncAttributeMaxDynamicSharedMemorySize, GEMM_SMEM);

    split_x_kernel<<<(M_TOTAL * (D / 4)) / 256, 256>>>(x);
    split_w_kernel<<<dim3((D * (D / 4)) / 256, 3), 256>>>(Wq, Wk, Wv);
    qkv_mma_kernel<<<dim3(4, 64, 3), 256, GEMM_SMEM>>>(bq, bk, bv);
    norm_kernel<<<dim3(M_TOTAL, 2), 256>>>();
    scores_mma_kernel<<<dim3(8, 16, 4), 256, GEMM_SMEM>>>();
    topk_kernel<<<M_TOTAL, 256>>>(out);
}

// round 8
// speedup vs baseline: 1.1630x; 1.1630x over previous
#include <cuda_runtime.h>
#include <cuda_bf16.h>
#include <cuda_fp16.h>
#include <cstdint>
#include <math.h>

#define BATCH 4
#define P 2048
#define D 1024
#define M_TOTAL (BATCH * P)     // 8192
#define NUM_ROUTES 8
#define NEG_BIG -3.0e38f
#define MASK_VAL -60000.0f

#define X_SCALE 16.0f           // 2^4
#define W_SCALE 1024.0f         // 2^10
#define INV_SCALE (1.0f / 16384.0f)  // 2^-14

#define OUT_W_OFF  (M_TOTAL * NUM_ROUTES)
#define OUT_F_OFF  (2 * M_TOTAL * NUM_ROUTES)

// ---------------- scratch (__device__ globals; no allocation allowed) -------
__device__ __half g_xs0[(size_t)M_TOTAL * D];
__device__ __half g_xs1[(size_t)M_TOTAL * D];
__device__ __half g_ws[3][2][(size_t)D * D];   // [which][split], scaled by 2^10
__device__ float g_q[(size_t)M_TOTAL * D];     // raw (unnormalized) fp32
__device__ float g_k[(size_t)M_TOTAL * D];     // raw (unnormalized) fp32
__device__ float g_v[(size_t)M_TOTAL * D];
__device__ float g_qn[M_TOTAL];                // row norms
__device__ float g_kn[M_TOTAL];
__device__ __half g_qh[(size_t)M_TOTAL * D];   // raw q, fp16
__device__ __half g_kh[(size_t)M_TOTAL * D];   // normalized k, fp16
__device__ __half g_scoresh[(size_t)BATCH * P * P];   // 32 MB (fp16 scores)

// ---------------- PTX helpers (compute_103-safe) ----------------------------
__device__ __forceinline__ uint32_t cvta_smem(const void* p) {
    return (uint32_t)__cvta_generic_to_shared(p);
}
__device__ __forceinline__ void cp16(uint32_t saddr, const void* gaddr) {
    asm volatile("cp.async.cg.shared.global [%0], [%1], 16;\n"
                 :: "r"(saddr), "l"(gaddr));
}
__device__ __forceinline__ void cp_commit() { asm volatile("cp.async.commit_group;\n"); }
__device__ __forceinline__ void cp_wait1() {
    asm volatile("cp.async.wait_group 1;\n" ::: "memory");
}
__device__ __forceinline__ void ldm4(uint32_t& r0, uint32_t& r1, uint32_t& r2, uint32_t& r3,
                                     uint32_t addr) {
    asm volatile("ldmatrix.sync.aligned.m8n8.x4.shared.b16 {%0,%1,%2,%3}, [%4];"
                 : "=r"(r0), "=r"(r1), "=r"(r2), "=r"(r3) : "r"(addr));
}
__device__ __forceinline__ void mma16816(float* d, const uint32_t* a, const uint32_t* b) {
    asm volatile(
        "mma.sync.aligned.m16n8k16.row.col.f32.f16.f16.f32 "
        "{%0,%1,%2,%3}, {%4,%5,%6,%7}, {%8,%9}, {%0,%1,%2,%3};"
        : "+f"(d[0]), "+f"(d[1]), "+f"(d[2]), "+f"(d[3])
        : "r"(a[0]), "r"(a[1]), "r"(a[2]), "r"(a[3]), "r"(b[0]), "r"(b[1]));
}

// ---------------- split / convert helpers ------------------------------------
__device__ __forceinline__ void split2(float f, __half& a0, __half& a1) {
    a0 = __float2half_rn(f);
    a1 = __float2half_rn(f - __half2float(a0));
}
__device__ __forceinline__ uint2 pack4h(__half a, __half b, __half c, __half d) {
    uint2 r;
    r.x = (uint32_t)__half_as_ushort(a) | ((uint32_t)__half_as_ushort(b) << 16);
    r.y = (uint32_t)__half_as_ushort(c) | ((uint32_t)__half_as_ushort(d) << 16);
    return r;
}

__global__ __launch_bounds__(256) void split_x_kernel(const float* __restrict__ x) {
    size_t e = ((size_t)blockIdx.x * 256 + threadIdx.x) * 4;
    int row = (int)(e >> 10);
    int col = (int)(e & 1023);
    int xrow = row + (row >> 11) + 1;    // skip token 0 of each batch
    float4 f = *(const float4*)(x + (size_t)xrow * D + col);
    __half a0[4], a1[4];
    split2(f.x * X_SCALE, a0[0], a1[0]);
    split2(f.y * X_SCALE, a0[1], a1[1]);
    split2(f.z * X_SCALE, a0[2], a1[2]);
    split2(f.w * X_SCALE, a0[3], a1[3]);
    *(uint2*)(g_xs0 + e) = pack4h(a0[0], a0[1], a0[2], a0[3]);
    *(uint2*)(g_xs1 + e) = pack4h(a1[0], a1[1], a1[2], a1[3]);
}

__global__ __launch_bounds__(256) void split_w_kernel(
    const float* __restrict__ Wq, const float* __restrict__ Wk, const float* __restrict__ Wv) {
    const int z = blockIdx.y;
    const float* W = (z == 0) ? Wq : (z == 1) ? Wk : Wv;
    size_t e = ((size_t)blockIdx.x * 256 + threadIdx.x) * 4;
    float4 f = *(const float4*)(W + e);
    __half a0[4], a1[4];
    split2(f.x * W_SCALE, a0[0], a1[0]);
    split2(f.y * W_SCALE, a0[1], a1[1]);
    split2(f.z * W_SCALE, a0[2], a1[2]);
    split2(f.w * W_SCALE, a0[3], a1[3]);
    *(uint2*)(g_ws[z][0] + e) = pack4h(a0[0], a0[1], a0[2], a0[3]);
    *(uint2*)(g_ws[z][1] + e) = pack4h(a1[0], a1[1], a1[2], a1[3]);
}

// ---------------- GEMM machinery: BK=64, 3-stage cp.async pipeline -----------
#define STAGES 3
#define SM_PER_BUF 55296
#define A_BYTES 18432
#define GEMM_SMEM (STAGES * SM_PER_BUF)

__device__ __forceinline__ void load_chunk(uint32_t st,
    const __half* __restrict__ Ag, const __half* __restrict__ Bg,
    int m0, int n0, int kc, int tid)
{
    const uint32_t sA = st, sB = st + A_BYTES;
#pragma unroll
    for (int t = 0; t < 4; t++) {
        int li = tid + t * 256;
        int row = li >> 3, seg = li & 7;
        cp16(sA + row * 144 + seg * 16, Ag + (size_t)(m0 + row) * D + kc * 64 + seg * 8);
    }
#pragma unroll
    for (int t = 0; t < 8; t++) {
        int li = tid + t * 256;
        int row = li >> 3, seg = li & 7;
        cp16(sB + row * 144 + seg * 16, Bg + (size_t)(n0 + row) * D + kc * 64 + seg * 8);
    }
}

__device__ __forceinline__ void compute_chunk(uint32_t st,
                                              float acc[4][8][4], int wr, int wc, int lane)
{
    const uint32_t sA = st, sB = st + A_BYTES;
    const int lr = lane & 15;
    const int lh = (lane >> 4) * 16;
#pragma unroll
    for (int ks = 0; ks < 4; ks++) {
        uint32_t a[4][4];
#pragma unroll
        for (int mi = 0; mi < 4; mi++)
            ldm4(a[mi][0], a[mi][1], a[mi][2], a[mi][3],
                 sA + (uint32_t)(wr * 64 + mi * 16 + lr) * 144 + ks * 32 + lh);
        uint32_t b[8][2];
#pragma unroll
        for (int njp = 0; njp < 4; njp++) {
            uint32_t r0, r1, r2, r3;
            ldm4(r0, r1, r2, r3,
                 sB + (uint32_t)(wc * 64 + njp * 16 + lr) * 144 + ks * 32 + lh);
            b[njp * 2][0] = r0; b[njp * 2][1] = r2;
            b[njp * 2 + 1][0] = r1; b[njp * 2 + 1][1] = r3;
        }
#pragma unroll
        for (int mi = 0; mi < 4; mi++)
#pragma unroll
            for (int nj = 0; nj < 8; nj++)
                mma16816(acc[mi][nj], a[mi], b[nj]);
    }
}

// ---------------- QKV GEMM (fp16x2 split; q/k: 3 combos, v: 1) ---------------
// grid (4, 64, 3); 16 k64-chunks per combo pass
__global__ __launch_bounds__(256, 1) void qkv_mma_kernel(
    const float* __restrict__ bq, const float* __restrict__ bk, const float* __restrict__ bv)
{
    extern __shared__ char dynsm[];
    const uint32_t sbase = cvta_smem(dynsm);

    const int z = blockIdx.z;
    const int m0 = blockIdx.y * 128, n0 = blockIdx.x * 256;
    const int tid = threadIdx.x, wid = tid >> 5, lane = tid & 31;
    const int wr = wid >> 2, wc = wid & 3;

    const __half* As[2] = { g_xs0, g_xs1 };
    const __half* Bs[2] = { g_ws[z][0], g_ws[z][1] };
    float* Cmat = (z == 0) ? g_q : (z == 1) ? g_k : g_v;
    const float* bias = (z == 0) ? bq : (z == 1) ? bk : bv;

    const int ca[3] = {0, 0, 1};
    const int cb[3] = {0, 1, 0};
    const int ncombo = (z == 2) ? 1 : 3;
    const int nch = ncombo * 16;

    float acc[4][8][4];
#pragma unroll
    for (int mi = 0; mi < 4; mi++)
#pragma unroll
        for (int nj = 0; nj < 8; nj++)
#pragma unroll
            for (int t = 0; t < 4; t++) acc[mi][nj][t] = 0.0f;

#pragma unroll
    for (int s = 0; s < STAGES - 1; s++) {
        load_chunk(sbase + s * SM_PER_BUF, As[ca[s >> 4]], Bs[cb[s >> 4]],
                   m0, n0, s & 15, tid);
        cp_commit();
    }

    for (int ch = 0; ch < nch; ch++) {
        cp_wait1();
        __syncthreads();
        const int ld = ch + STAGES - 1;
        if (ld < nch)
            load_chunk(sbase + (ld % 3) * SM_PER_BUF, As[ca[ld >> 4]], Bs[cb[ld >> 4]],
                       m0, n0, ld & 15, tid);
        cp_commit();
        compute_chunk(sbase + (ch % 3) * SM_PER_BUF, acc, wr, wc, lane);
    }

#pragma unroll
    for (int nj = 0; nj < 8; nj++) {
        const int n = n0 + wc * 64 + nj * 8 + (lane & 3) * 2;
        const float2 b2 = *(const float2*)(bias + n);
#pragma unroll
        for (int mi = 0; mi < 4; mi++) {
            const int row0 = m0 + wr * 64 + mi * 16 + (lane >> 2);
            float2 v0 = { fmaf(acc[mi][nj][0], INV_SCALE, b2.x),
                          fmaf(acc[mi][nj][1], INV_SCALE, b2.y) };
            float2 v1 = { fmaf(acc[mi][nj][2], INV_SCALE, b2.x),
                          fmaf(acc[mi][nj][3], INV_SCALE, b2.y) };
            *(float2*)(Cmat + (size_t)row0 * D + n) = v0;
            *(float2*)(Cmat + (size_t)(row0 + 8) * D + n) = v1;
        }
    }
}

// ---------------- scores GEMM (q_raw . k_hat, fp16) + diag mask --------------
// Row-ranking identical to cosine similarity (q norm is a per-row scale).
// grid (8, 16, 4); 16 k64-chunks
__global__ __launch_bounds__(256, 1) void scores_mma_kernel()
{
    extern __shared__ char dynsm[];
    const uint32_t sbase = cvta_smem(dynsm);

    const int b = blockIdx.z;
    const int m0 = blockIdx.y * 128, n0 = blockIdx.x * 256;
    const int tid = threadIdx.x, wid = tid >> 5, lane = tid & 31;
    const int wr = wid >> 2, wc = wid & 3;

    const __half* Ag = g_qh + (size_t)b * P * D;
    const __half* Bg = g_kh + (size_t)b * P * D;
    __half* Cmat = g_scoresh + (size_t)b * P * P;

    float acc[4][8][4];
#pragma unroll
    for (int mi = 0; mi < 4; mi++)
#pragma unroll
        for (int nj = 0; nj < 8; nj++)
#pragma unroll
            for (int t = 0; t < 4; t++) acc[mi][nj][t] = 0.0f;

#pragma unroll
    for (int s = 0; s < STAGES - 1; s++) {
        load_chunk(sbase + s * SM_PER_BUF, Ag, Bg, m0, n0, s, tid);
        cp_commit();
    }

    for (int ch = 0; ch < 16; ch++) {
        cp_wait1();
        __syncthreads();
        const int ld = ch + STAGES - 1;
        if (ld < 16)
            load_chunk(sbase + (ld % 3) * SM_PER_BUF, Ag, Bg, m0, n0, ld, tid);
        cp_commit();
        compute_chunk(sbase + (ch % 3) * SM_PER_BUF, acc, wr, wc, lane);
    }

#pragma unroll
    for (int nj = 0; nj < 8; nj++) {
        const int n = n0 + wc * 64 + nj * 8 + (lane & 3) * 2;
#pragma unroll
        for (int mi = 0; mi < 4; mi++) {
            const int row0 = m0 + wr * 64 + mi * 16 + (lane >> 2);
            float2 v0 = { acc[mi][nj][0], acc[mi][nj][1] };
            float2 v1 = { acc[mi][nj][2], acc[mi][nj][3] };
            if (row0 == n) v0.x = MASK_VAL;
            if (row0 == n + 1) v0.y = MASK_VAL;
            if (row0 + 8 == n) v1.x = MASK_VAL;
            if (row0 + 8 == n + 1) v1.y = MASK_VAL;
            *(__half2*)(Cmat + (size_t)row0 * P + n) = __floats2half2_rn(v0.x, v0.y);
            *(__half2*)(Cmat + (size_t)(row0 + 8) * P + n) = __floats2half2_rn(v1.x, v1.y);
        }
    }
}

// ---------------- norms + fp16 operand prep (no fp32 writes) -----------------
// y=0: q row -> g_qn, g_qh (raw fp16). y=1: k row -> g_kn, g_kh (normalized fp16)
__global__ __launch_bounds__(256) void norm_kernel() {
    const int r = blockIdx.x;
    const int tid = threadIdx.x;
    const bool isq = (blockIdx.y == 0);
    const float* row = (isq ? g_q : g_k) + (size_t)r * D;
    __half* hrow = (isq ? g_qh : g_kh) + (size_t)r * D;

    float4 v = ((const float4*)row)[tid];
    float s = v.x * v.x + v.y * v.y + v.z * v.z + v.w * v.w;
#pragma unroll
    for (int o = 16; o > 0; o >>= 1) s += __shfl_xor_sync(0xffffffffu, s, o);

    __shared__ float ws[8];
    if ((tid & 31) == 0) ws[tid >> 5] = s;
    __syncthreads();
    float tot = 0.0f;
#pragma unroll
    for (int w = 0; w < 8; w++) tot += ws[w];
    const float nrm = fmaxf(sqrtf(tot), 1e-12f);

    if (tid == 0) { if (isq) g_qn[r] = nrm; else g_kn[r] = nrm; }

    if (isq) {
        *(uint2*)(hrow + tid * 4) = pack4h(__float2half_rn(v.x), __float2half_rn(v.y),
                                           __float2half_rn(v.z), __float2half_rn(v.w));
    } else {
        const float inv = 1.0f / nrm;
        *(uint2*)(hrow + tid * 4) = pack4h(__float2half_rn(v.x * inv), __float2half_rn(v.y * inv),
                                           __float2half_rn(v.z * inv), __float2half_rn(v.w * inv));
    }
}

// ---------------- fused top-16 -> fp32 cosine rescue -> top-8 -> features ----
__global__ __launch_bounds__(256) void topk_kernel(float* __restrict__ out) {
    __shared__ float s_q[D];
    __shared__ float s_cv[128];
    __shared__ int   s_ci[128];
    __shared__ int   s_c16[16];
    __shared__ float s_resc[16];
    __shared__ int   s_routes[8];
    __shared__ float s_vals[8];
    __shared__ float s_wn[8];

    const int r = blockIdx.x;
    const int b = r >> 11;
    const int tid = threadIdx.x, wid = tid >> 5, lane = tid & 31;
    const __half* srow = g_scoresh + (size_t)r * P;

    // stage raw q row for the rescue dots
    ((float4*)s_q)[tid] = ((const float4*)(g_q + (size_t)r * D))[tid];

    // Stage A: each warp extracts top-16 of its 256-element segment
    const int base = wid * 256 + lane * 8;
    float v[8];
    {
        uint4 u = *(const uint4*)(srow + base);   // 8 halves
        float2 f0 = __half22float2(*(__half2*)&u.x);
        float2 f1 = __half22float2(*(__half2*)&u.y);
        float2 f2 = __half22float2(*(__half2*)&u.z);
        float2 f3 = __half22float2(*(__half2*)&u.w);
        v[0] = f0.x; v[1] = f0.y; v[2] = f1.x; v[3] = f1.y;
        v[4] = f2.x; v[5] = f2.y; v[6] = f3.x; v[7] = f3.y;
    }
    for (int it = 0; it < 16; it++) {
        float bvv = v[0]; int bj = 0;
#pragma unroll
        for (int j = 1; j < 8; j++) if (v[j] > bvv) { bvv = v[j]; bj = j; }
        int bi = base + bj;
#pragma unroll
        for (int o = 16; o; o >>= 1) {
            float ov = __shfl_xor_sync(0xffffffffu, bvv, o);
            int oi = __shfl_xor_sync(0xffffffffu, bi, o);
            if (ov > bvv || (ov == bvv && oi < bi)) { bvv = ov; bi = oi; }
        }
        if (lane == 0) { s_cv[wid * 16 + it] = bvv; s_ci[wid * 16 + it] = bi; }
        if (bi >= base && bi < base + 8) v[bi - base] = NEG_BIG;
    }
    __syncthreads();

    // Stage B: warp 0 merges 128 candidates -> global top-16
    if (wid == 0) {
        float cv[4]; int ci[4];
#pragma unroll
        for (int j = 0; j < 4; j++) { cv[j] = s_cv[lane * 4 + j]; ci[j] = s_ci[lane * 4 + j]; }
        for (int it = 0; it < 16; it++) {
            float bvv = cv[0]; int bi = ci[0];
#pragma unroll
            for (int j = 1; j < 4; j++)
                if (cv[j] > bvv || (cv[j] == bvv && ci[j] < bi)) { bvv = cv[j]; bi = ci[j]; }
#pragma unroll
            for (int o = 16; o; o >>= 1) {
                float ov = __shfl_xor_sync(0xffffffffu, bvv, o);
                int oi = __shfl_xor_sync(0xffffffffu, bi, o);
                if (ov > bvv || (ov == bvv && oi < bi)) { bvv = ov; bi = oi; }
            }
            if (lane == 0) s_c16[it] = bi;
#pragma unroll
            for (int j = 0; j < 4; j++) if (ci[j] == bi) cv[j] = NEG_BIG;
        }
    }
    __syncthreads();

    // Stage C: fp32 rescue — exact cosine scores for 16 candidates (2 per warp)
    const float invqn = 1.0f / g_qn[r];
#pragma unroll
    for (int h = 0; h < 2; h++) {
        const int c = wid + h * 8;
        const int cand = s_c16[c];
        const float* krow = g_k + ((size_t)(b * P + cand)) * D;
        float acc = 0.0f;
#pragma unroll
        for (int i = 0; i < 8; i++) {
            const int off = i * 128 + lane * 4;
            float4 qa = *(const float4*)(s_q + off);
            float4 ka = *(const float4*)(krow + off);
            acc += qa.x * ka.x + qa.y * ka.y + qa.z * ka.z + qa.w * ka.w;
        }
#pragma unroll
        for (int o = 16; o; o >>= 1) acc += __shfl_xor_sync(0xffffffffu, acc, o);
        if (lane == 0) s_resc[c] = acc * invqn / g_kn[b * P + cand];
    }
    __syncthreads();

    // Stage D: warp 0 re-ranks 16 rescued candidates -> exact top-8
    if (wid == 0) {
        float val = (lane < 16) ? s_resc[lane] : NEG_BIG;
        int idx = (lane < 16) ? s_c16[lane] : 0x7fffffff;
        for (int rank = 0; rank < NUM_ROUTES; rank++) {
            float bvv = val; int bi = idx;
#pragma unroll
            for (int o = 16; o; o >>= 1) {
                float ov = __shfl_xor_sync(0xffffffffu, bvv, o);
                int oi = __shfl_xor_sync(0xffffffffu, bi, o);
                if (ov > bvv || (ov == bvv && oi < bi)) { bvv = ov; bi = oi; }
            }
            if (lane == 0) { s_routes[rank] = bi; s_vals[rank] = bvv; }
            if (idx == bi) val = NEG_BIG;
        }
    }
    __syncthreads();

    if (tid < NUM_ROUTES) {
        const float mx = s_vals[0];
        float sum = 0.0f;
#pragma unroll
        for (int j = 0; j < NUM_ROUTES; j++) sum += __expf((s_vals[j] - mx) * 10.0f);
        const float wn = __expf((s_vals[tid] - mx) * 10.0f) / sum;
        out[(size_t)r * NUM_ROUTES + tid] = (float)s_routes[tid];
        out[OUT_W_OFF + (size_t)r * NUM_ROUTES + tid] = wn;
        s_wn[tid] = wn;
    }
    __syncthreads();

    // Stage E: features
    const float* vb = g_v + (size_t)b * P * D;
    int rt[8]; float ww[8];
#pragma unroll
    for (int i = 0; i < 8; i++) { rt[i] = s_routes[i]; ww[i] = s_wn[i]; }
    const int d0 = tid * 4;
    float4 acc4 = {0.0f, 0.0f, 0.0f, 0.0f};
#pragma unroll
    for (int i = 0; i < 8; i++) {
        float4 vv = *(const float4*)(vb + (size_t)rt[i] * D + d0);
        acc4.x = fmaf(ww[i], vv.x, acc4.x);
        acc4.y = fmaf(ww[i], vv.y, acc4.y);
        acc4.z = fmaf(ww[i], vv.z, acc4.z);
        acc4.w = fmaf(ww[i], vv.w, acc4.w);
    }
    *(float4*)(out + OUT_F_OFF + (size_t)r * D + d0) = acc4;
}

// ---------------------------------------------------------------------------
extern "C" void kernel_launch(void* const* d_in, const int* in_sizes, int n_in,
                              void* d_out, int out_size) {
    const float* x  = (const float*)d_in[0];
    const float* Wq = (const float*)d_in[1];
    const float* bq = (const float*)d_in[2];
    const float* Wk = (const float*)d_in[3];
    const float* bk = (const float*)d_in[4];
    const float* Wv = (const float*)d_in[5];
    const float* bv = (const float*)d_in[6];
    float* out = (float*)d_out;

    cudaFuncSetAttribute(qkv_mma_kernel, cudaFuncAttributeMaxDynamicSharedMemorySize, GEMM_SMEM);
    cudaFuncSetAttribute(scores_mma_kernel, cudaFuncAttributeMaxDynamicSharedMemorySize, GEMM_SMEM);

    split_x_kernel<<<(M_TOTAL * (D / 4)) / 256, 256>>>(x);
    split_w_kernel<<<dim3((D * (D / 4)) / 256, 3), 256>>>(Wq, Wk, Wv);
    qkv_mma_kernel<<<dim3(4, 64, 3), 256, GEMM_SMEM>>>(bq, bk, bv);
    norm_kernel<<<dim3(M_TOTAL, 2), 256>>>();
    scores_mma_kernel<<<dim3(8, 16, 4), 256, GEMM_SMEM>>>();
    topk_kernel<<<M_TOTAL, 256>>>(out);
}